// round 14
// baseline (speedup 1.0000x reference)
#include <cuda_runtime.h>
#include <cuda_bf16.h>
#include <cuda_fp16.h>
#include <cuda_fp8.h>
#include <math.h>
#include <stdint.h>

// Problem constants
#define Bn   4
#define Ln   6400
#define Cn   768
#define NHn  6
#define NPn  4
#define DHn  128
#define HSn  80
#define WSn  80
#define BLn  (Bn * Ln)          // 25600 rows
#define OAW  72                 // 48 offset cols + 24 attn-weight cols

#define WSCALE     64.0f
#define INV_WSCALE (1.0f / 64.0f)

// ---------------------------------------------------------------------------
// Scratch (static device globals)
// ---------------------------------------------------------------------------
__device__ uint8_t g_qb8[BLn * Cn];     // layernorm(x), e4m3
__device__ uint8_t g_fb8[BLn * Cn];     // layernorm(feat), e4m3
__device__ uint8_t g_val8[BLn * Cn];    // value [B][NH][L][DH], e4m3
__device__ uint8_t g_attn8[BLn * Cn];   // sampled attn [B*L][C], e4m3
__device__ float   g_offaw[BLn * OAW];  // offsets+logits, fp32
__device__ uint8_t g_wvt8[Cn * Cn];     // (Wv*64)^T   [N][K] e4m3
__device__ uint8_t g_woutt8[Cn * Cn];   // (Wout*64)^T [N][K] e4m3
__device__ uint8_t g_wct8[128 * Cn];    // ([Woff|Waw|0]*64)^T [128][K] e4m3
__device__ float   g_bc[OAW];           // combined bias

// ---------------------------------------------------------------------------
// PTX helpers
// ---------------------------------------------------------------------------
__device__ __forceinline__ uint32_t s2u(const void* p) {
    uint32_t a;
    asm("{ .reg .u64 t; cvta.to.shared.u64 t, %1; cvt.u32.u64 %0, t; }"
        : "=r"(a) : "l"(p));
    return a;
}
__device__ __forceinline__ void ldsm_x4(uint32_t* r, uint32_t addr) {
    asm volatile("ldmatrix.sync.aligned.m8n8.x4.shared.b16 {%0,%1,%2,%3}, [%4];"
        : "=r"(r[0]), "=r"(r[1]), "=r"(r[2]), "=r"(r[3]) : "r"(addr));
}
__device__ __forceinline__ void mma_fp8(float* c, const uint32_t* a, const uint32_t* b) {
    asm volatile(
        "mma.sync.aligned.m16n8k32.row.col.f32.e4m3.e4m3.f32 "
        "{%0,%1,%2,%3}, {%4,%5,%6,%7}, {%8,%9}, {%0,%1,%2,%3};"
        : "+f"(c[0]), "+f"(c[1]), "+f"(c[2]), "+f"(c[3])
        : "r"(a[0]), "r"(a[1]), "r"(a[2]), "r"(a[3]), "r"(b[0]), "r"(b[1]));
}
__device__ __forceinline__ void cp16(uint32_t smem, const void* g) {
    asm volatile("cp.async.cg.shared.global [%0], [%1], 16;" :: "r"(smem), "l"(g));
}
#define CP_COMMIT()  asm volatile("cp.async.commit_group;" ::: "memory")
#define CP_WAIT0()   asm volatile("cp.async.wait_group 0;" ::: "memory")

__device__ __forceinline__ uint32_t pack_fp8x4(float a, float b, float c, float d) {
    __nv_fp8x2_storage_t lo = __nv_cvt_float2_to_fp8x2(make_float2(a, b),
                                                       __NV_SATFINITE, __NV_E4M3);
    __nv_fp8x2_storage_t hi = __nv_cvt_float2_to_fp8x2(make_float2(c, d),
                                                       __NV_SATFINITE, __NV_E4M3);
    return (uint32_t)lo | ((uint32_t)hi << 16);
}
__device__ __forceinline__ float2 fp8x2_to_float2(uint16_t v) {
    __half2_raw h = __nv_cvt_fp8x2_to_halfraw2((__nv_fp8x2_storage_t)v, __NV_E4M3);
    return __half22float2(*reinterpret_cast<__half2*>(&h));
}

// ---------------------------------------------------------------------------
// Fused prep + LayerNorm kernel. Flat blockIdx dispatch (see R10 notes).
// ---------------------------------------------------------------------------
__global__ void __launch_bounds__(256) prep_ln_kernel(
    const float* __restrict__ x,    const float* __restrict__ feat,
    const float* __restrict__ qn_w, const float* __restrict__ qn_b,
    const float* __restrict__ fn_w, const float* __restrict__ fn_b,
    const float* __restrict__ Wv,   const float* __restrict__ Wout,
    const float* __restrict__ Woff, const float* __restrict__ boff,
    const float* __restrict__ Waw,  const float* __restrict__ baw,
    uint8_t* __restrict__ qb8, uint8_t* __restrict__ fb8,
    uint8_t* __restrict__ wvt8, uint8_t* __restrict__ woutt8,
    uint8_t* __restrict__ wct8, float* __restrict__ bc)
{
    __shared__ float tsh[32 * 33];
    const int blk = blockIdx.x;
    const int tid = threadIdx.x;

    if (blk < 6400) {
        const float* in; const float* w; const float* b; uint8_t* out;
        int base;
        if (blk < 3200) { in = x;    w = qn_w; b = qn_b; out = qb8; base = blk; }
        else            { in = feat; w = fn_w; b = fn_b; out = fb8; base = blk - 3200; }
        const int wid = tid >> 5, lane = tid & 31;
        const int row = base * 8 + wid;
        const float4* p = (const float4*)(in + (size_t)row * Cn);

        float4 v[6];
        #pragma unroll
        for (int i = 0; i < 6; i++) v[i] = p[i * 32 + lane];
        float s1 = 0.f, s2 = 0.f;
        #pragma unroll
        for (int i = 0; i < 6; i++) {
            s1 += v[i].x + v[i].y + v[i].z + v[i].w;
            s2 += v[i].x * v[i].x + v[i].y * v[i].y
                + v[i].z * v[i].z + v[i].w * v[i].w;
        }
        #pragma unroll
        for (int o = 16; o > 0; o >>= 1) {
            s1 += __shfl_xor_sync(0xffffffffu, s1, o);
            s2 += __shfl_xor_sync(0xffffffffu, s2, o);
        }
        float mu = s1 * (1.0f / Cn);
        float rs = rsqrtf(s2 * (1.0f / Cn) - mu * mu + 1e-6f);

        const float4* wv = (const float4*)w;
        const float4* bv = (const float4*)b;
        uint32_t* o = (uint32_t*)(out + (size_t)row * Cn);
        #pragma unroll
        for (int i = 0; i < 6; i++) {
            float4 ww = wv[i * 32 + lane];
            float4 bb = bv[i * 32 + lane];
            o[i * 32 + lane] = pack_fp8x4(
                (v[i].x - mu) * rs * ww.x + bb.x,
                (v[i].y - mu) * rs * ww.y + bb.y,
                (v[i].z - mu) * rs * ww.z + bb.z,
                (v[i].w - mu) * rs * ww.w + bb.w);
        }
    } else if (blk < 7552) {
        const float* W;
        uint8_t* Wt;
        int t;
        if (blk < 6976) { W = Wv;   Wt = wvt8;   t = blk - 6400; }
        else            { W = Wout; Wt = woutt8; t = blk - 6976; }
        int bx = t % 24, by = t / 24;
        int tx = tid & 31, ty4 = tid >> 5;
        #pragma unroll
        for (int r = 0; r < 4; r++) {
            int ty = ty4 + r * 8;
            tsh[ty * 33 + tx] = W[(size_t)(by * 32 + ty) * Cn + bx * 32 + tx];
        }
        __syncthreads();
        #pragma unroll
        for (int r = 0; r < 4; r++) {
            int ty = ty4 + r * 8;
            Wt[(size_t)(bx * 32 + ty) * Cn + by * 32 + tx] =
                (uint8_t)__nv_cvt_float_to_fp8(tsh[tx * 33 + ty] * WSCALE,
                                               __NV_SATFINITE, __NV_E4M3);
        }
    } else {
        int idx = (blk - 7552) * 256 + tid;     // 0 .. 128*768-1
        int j = idx / Cn, k = idx % Cn;
        float v = 0.f;
        if (j < 48)       v = Woff[(size_t)k * 48 + j];
        else if (j < OAW) v = Waw[(size_t)k * 24 + (j - 48)];
        wct8[idx] = (uint8_t)__nv_cvt_float_to_fp8(v * WSCALE,
                                                   __NV_SATFINITE, __NV_E4M3);
        if (idx < OAW) bc[idx] = (idx < 48) ? boff[idx] : baw[idx - 48];
    }
}

// ---------------------------------------------------------------------------
// FP8 HMMA GEMM, CTA 128x128, BK=64/stage, 4-stage cp.async pipeline processed
// in PAIRS (one barrier per 2 buffers), hoisted ldmatrix offsets.
// __launch_bounds__(256,2): 2 CTAs/SM. At the legacy mma.sync rate plateau.
// STAGE 0 (grid 7 x 200): cCol 0..5 value GEMM, cCol 6 offaw GEMM.
// STAGE 1 (grid 6 x 200): fused residual out GEMM.
// ---------------------------------------------------------------------------
#define PITCHB 80
#define STGB   (128 * PITCHB)
#define NIT    12
#define FP8_SMEM (4 * 2 * STGB)     // 81920 B

template <int STAGE>
__global__ void __launch_bounds__(256, 2) gemm_fp8(
    const uint8_t* __restrict__ A0,   // stage0: fb8   | stage1: attn8
    const uint8_t* __restrict__ B0,   // stage0: wvt8  | stage1: woutt8
    const float* __restrict__ bias0,  // stage0: bv    | stage1: bout
    void* __restrict__ C0,            // stage0: val8  | stage1: out (fp32)
    const uint8_t* __restrict__ A1,   // stage0: qb8
    const uint8_t* __restrict__ B1,   // stage0: wct8
    const float* __restrict__ bias1,  // stage0: bc
    float* __restrict__ C1,           // stage0: oaw
    const float* __restrict__ xin,
    const float* __restrict__ gamma)
{
    extern __shared__ __align__(16) uint8_t dynsm[];

    const int tid  = threadIdx.x;
    const int wid  = tid >> 5, lane = tid & 31;
    const int wm   = wid & 3;
    const int wn   = wid >> 2;
    const int cCol = blockIdx.x, cRow = blockIdx.y;
    const bool off = (STAGE == 0) && (cCol == 6);

    const uint8_t* Ab = (off ? A1 : A0) + (size_t)cRow * 128 * Cn;
    const uint8_t* Bb = off ? B1 : (B0 + (size_t)cCol * 128 * Cn);
    const float* bias = off ? bias1 : bias0;
    const uint32_t smemBase = s2u(dynsm);

    const int row_c[2] = { tid >> 2, (tid + 256) >> 2 };
    const int q = tid & 3;

    auto issue = [&](int i) {
        uint32_t ab = smemBase + (uint32_t)(i & 3) * (2 * STGB);
        uint32_t bb = ab + STGB;
        int k0 = i * 64;
        #pragma unroll
        for (int it = 0; it < 2; it++) {
            int row = row_c[it];
            uint32_t so = (uint32_t)(row * PITCHB + q * 16);
            cp16(ab + so, Ab + (size_t)row * Cn + k0 + q * 16);
            cp16(bb + so, Bb + (size_t)row * Cn + k0 + q * 16);
        }
    };

    float acc[2][8][4];
    #pragma unroll
    for (int mi = 0; mi < 2; mi++)
        #pragma unroll
        for (int n8 = 0; n8 < 8; n8++)
            #pragma unroll
            for (int j = 0; j < 4; j++) acc[mi][n8][j] = 0.f;

    // Hoisted per-lane ldmatrix byte offsets within a stage buffer
    const int lrow = lane & 7, grp = lane >> 3;
    const int rA = wm * 32 + (grp & 1) * 8 + lrow;
    const int cA = (grp >> 1) * 8;
    const int rB = wn * 64 + ((lane >> 4) & 1) * 8 + lrow;
    const int cB = (grp & 1) * 8;
    uint32_t oA[2], oB[4];
    #pragma unroll
    for (int mi = 0; mi < 2; mi++)
        oA[mi] = (uint32_t)((rA + mi * 16) * PITCHB + cA * 2);
    #pragma unroll
    for (int nj = 0; nj < 4; nj++)
        oB[nj] = (uint32_t)((rB + nj * 16) * PITCHB + cB * 2) + STGB;

    issue(0); CP_COMMIT();
    issue(1); CP_COMMIT();

    for (int ip = 0; ip < NIT; ip += 2) {
        CP_WAIT0();              // buffers ip, ip+1 landed
        __syncthreads();
        if (ip + 2 < NIT) {
            issue(ip + 2); CP_COMMIT();
            issue(ip + 3); CP_COMMIT();
        }
        #pragma unroll
        for (int d = 0; d < 2; d++) {
            uint32_t base = smemBase + (uint32_t)((ip + d) & 3) * (2 * STGB);
            #pragma unroll
            for (int kk = 0; kk < 2; kk++) {
                uint32_t kof = kk * 32;
                uint32_t afr[2][4], bfr[4][4];
                #pragma unroll
                for (int mi = 0; mi < 2; mi++)
                    ldsm_x4(afr[mi], base + oA[mi] + kof);
                #pragma unroll
                for (int nj = 0; nj < 4; nj++)
                    ldsm_x4(bfr[nj], base + oB[nj] + kof);
                #pragma unroll
                for (int mi = 0; mi < 2; mi++)
                    #pragma unroll
                    for (int n8 = 0; n8 < 8; n8++)
                        mma_fp8(acc[mi][n8], afr[mi], &bfr[n8 >> 1][(n8 & 1) * 2]);
            }
        }
    }

    // ---------------- epilogue ----------------
    const int quad = lane >> 2, tcol = (lane & 3) * 2;
    if (STAGE == 0 && off) {
        #pragma unroll
        for (int mi = 0; mi < 2; mi++) {
            #pragma unroll
            for (int n8 = 0; n8 < 8; n8++) {
                int colt = wn * 64 + n8 * 8 + tcol;
                if (colt >= OAW) continue;
                #pragma unroll
                for (int half = 0; half < 2; half++) {
                    int row = cRow * 128 + wm * 32 + mi * 16 + quad + half * 8;
                    float v0 = acc[mi][n8][half * 2 + 0] * INV_WSCALE;
                    float v1 = acc[mi][n8][half * 2 + 1] * INV_WSCALE;
                    float* dst = C1 + (size_t)row * OAW;
                    dst[colt] = v0 + bias[colt];
                    if (colt + 1 < OAW) dst[colt + 1] = v1 + bias[colt + 1];
                }
            }
        }
    } else if (STAGE == 0) {
        // value: stage fp8 tile in SMEM, then coalesced 16B row stores
        __syncthreads();
        uint8_t* st = dynsm;                 // [128][128] fp8
        #pragma unroll
        for (int mi = 0; mi < 2; mi++) {
            #pragma unroll
            for (int n8 = 0; n8 < 8; n8++) {
                int colt = wn * 64 + n8 * 8 + tcol;
                int col  = cCol * 128 + colt;
                #pragma unroll
                for (int half = 0; half < 2; half++) {
                    int rloc = wm * 32 + mi * 16 + quad + half * 8;
                    float f0 = acc[mi][n8][half * 2 + 0] * INV_WSCALE + bias[col];
                    float f1 = acc[mi][n8][half * 2 + 1] * INV_WSCALE + bias[col + 1];
                    __nv_fp8x2_storage_t p = __nv_cvt_float2_to_fp8x2(
                        make_float2(f0, f1), __NV_SATFINITE, __NV_E4M3);
                    *(uint16_t*)(st + rloc * 128 + colt) = (uint16_t)p;
                }
            }
        }
        __syncthreads();
        #pragma unroll
        for (int it = 0; it < 4; it++) {
            int idx  = tid + it * 256;       // 0..1023 (16B chunks)
            int rloc = idx >> 3, c16 = idx & 7;
            int m = cRow * 128 + rloc;
            int b = m / Ln, l = m % Ln;
            uint4 v = *(uint4*)(st + rloc * 128 + c16 * 16);
            *(uint4*)((uint8_t*)C0 +
                ((size_t)(b * NHn + cCol) * Ln + l) * DHn + c16 * 16) = v;
        }
    } else {
        #pragma unroll
        for (int mi = 0; mi < 2; mi++) {
            #pragma unroll
            for (int n8 = 0; n8 < 8; n8++) {
                int colt = wn * 64 + n8 * 8 + tcol;
                int col  = cCol * 128 + colt;
                #pragma unroll
                for (int half = 0; half < 2; half++) {
                    int row = cRow * 128 + wm * 32 + mi * 16 + quad + half * 8;
                    float v0 = acc[mi][n8][half * 2 + 0] * INV_WSCALE;
                    float v1 = acc[mi][n8][half * 2 + 1] * INV_WSCALE;
                    size_t idx = (size_t)row * Cn + col;
                    float2 xv = *(const float2*)(xin + idx);
                    float2 r;
                    r.x = xv.x + gamma[col]     * (v0 + bias[col]);
                    r.y = xv.y + gamma[col + 1] * (v1 + bias[col + 1]);
                    *(float2*)((float*)C0 + idx) = r;
                }
            }
        }
    }
}

// ---------------------------------------------------------------------------
// Bilinear sampling + softmax, BRANCHLESS + BATCHED: compute all 16 clamped
// addresses + masked weights first, then issue all 16 gathers back-to-back
// (MLP ~16 hides L2 latency), then convert + accumulate.
// One warp per (b,l,h); lane owns 4 channels. value e4m3, attn e4m3.
// ---------------------------------------------------------------------------
__global__ void __launch_bounds__(256) sample_kernel(
    const float* __restrict__ refp, const float* __restrict__ offaw,
    const uint8_t* __restrict__ value, uint8_t* __restrict__ attn)
{
    int gw   = (blockIdx.x * 256 + threadIdx.x) >> 5;
    int lane = threadIdx.x & 31;
    if (gw >= BLn * NHn) return;
    int h  = gw % NHn;
    int bl = gw / NHn;
    int b  = bl / Ln;

    const float* oa = offaw + (size_t)bl * OAW;
    float lg0 = oa[48 + h * 4 + 0];
    float lg1 = oa[48 + h * 4 + 1];
    float lg2 = oa[48 + h * 4 + 2];
    float lg3 = oa[48 + h * 4 + 3];
    float mx = fmaxf(fmaxf(lg0, lg1), fmaxf(lg2, lg3));
    float e0 = expf(lg0 - mx), e1 = expf(lg1 - mx);
    float e2 = expf(lg2 - mx), e3 = expf(lg3 - mx);
    float inv = 1.0f / (e0 + e1 + e2 + e3);
    float aws[4] = {e0 * inv, e1 * inv, e2 * inv, e3 * inv};

    float rx = refp[bl * 2 + 0];
    float ry = refp[bl * 2 + 1];
    const uint8_t* vb = value + ((size_t)(b * NHn + h)) * Ln * DHn + lane * 4;

    // Phase 1: all 16 (address, weight) pairs
    const uint8_t* ptr[16];
    float wgt[16];
    #pragma unroll
    for (int p = 0; p < NPn; p++) {
        float ox = oa[h * 8 + p * 2 + 0];
        float oy = oa[h * 8 + p * 2 + 1];
        float lx = (rx + ox * (1.0f / WSn)) * (float)WSn - 0.5f;
        float ly = (ry + oy * (1.0f / HSn)) * (float)HSn - 0.5f;
        float x0f = floorf(lx), y0f = floorf(ly);
        float tx = lx - x0f, ty = ly - y0f;
        int x0 = (int)x0f, y0 = (int)y0f;
        float wp = aws[p];
        float cw[4] = {(1.f - tx) * (1.f - ty) * wp,
                       tx * (1.f - ty) * wp,
                       (1.f - tx) * ty * wp,
                       tx * ty * wp};
        #pragma unroll
        for (int c = 0; c < 4; c++) {
            int xi = x0 + (c & 1), yi = y0 + (c >> 1);
            bool valid = (xi >= 0) & (xi < WSn) & (yi >= 0) & (yi < HSn);
            int xc = min(max(xi, 0), WSn - 1);
            int yc = min(max(yi, 0), HSn - 1);
            ptr[p * 4 + c] = vb + (size_t)(yc * WSn + xc) * DHn;
            wgt[p * 4 + c] = valid ? cw[c] : 0.f;
        }
    }

    // Phase 2: all 16 gathers in flight
    uint32_t pk[16];
    #pragma unroll
    for (int i = 0; i < 16; i++) pk[i] = *(const uint32_t*)ptr[i];

    // Phase 3: convert + accumulate
    float4 acc = make_float4(0.f, 0.f, 0.f, 0.f);
    #pragma unroll
    for (int i = 0; i < 16; i++) {
        float2 f01 = fp8x2_to_float2((uint16_t)(pk[i] & 0xffffu));
        float2 f23 = fp8x2_to_float2((uint16_t)(pk[i] >> 16));
        float w = wgt[i];
        acc.x += w * f01.x; acc.y += w * f01.y;
        acc.z += w * f23.x; acc.w += w * f23.y;
    }
    *(uint32_t*)(attn + (size_t)bl * Cn + h * DHn + lane * 4) =
        pack_fp8x4(acc.x, acc.y, acc.z, acc.w);
}

// ---------------------------------------------------------------------------
// Launch: 4 kernels total
// ---------------------------------------------------------------------------
extern "C" void kernel_launch(void* const* d_in, const int* in_sizes, int n_in,
                              void* d_out, int out_size)
{
    const float* x     = (const float*)d_in[0];
    const float* refp  = (const float*)d_in[1];
    const float* feat  = (const float*)d_in[2];
    const float* qn_w  = (const float*)d_in[5];
    const float* qn_b  = (const float*)d_in[6];
    const float* fn_w  = (const float*)d_in[7];
    const float* fn_b  = (const float*)d_in[8];
    const float* gamma = (const float*)d_in[9];
    const float* Wv    = (const float*)d_in[10];
    const float* bv    = (const float*)d_in[11];
    const float* Woff  = (const float*)d_in[12];
    const float* boff  = (const float*)d_in[13];
    const float* Waw   = (const float*)d_in[14];
    const float* baw   = (const float*)d_in[15];
    const float* Wout  = (const float*)d_in[16];
    const float* bout  = (const float*)d_in[17];
    float* out = (float*)d_out;

    uint8_t *qb8, *fb8, *val8, *attn8, *wvt8, *woutt8, *wct8;
    float *oaw, *bc;
    cudaGetSymbolAddress((void**)&qb8,    g_qb8);
    cudaGetSymbolAddress((void**)&fb8,    g_fb8);
    cudaGetSymbolAddress((void**)&val8,   g_val8);
    cudaGetSymbolAddress((void**)&attn8,  g_attn8);
    cudaGetSymbolAddress((void**)&oaw,    g_offaw);
    cudaGetSymbolAddress((void**)&wvt8,   g_wvt8);
    cudaGetSymbolAddress((void**)&woutt8, g_woutt8);
    cudaGetSymbolAddress((void**)&wct8,   g_wct8);
    cudaGetSymbolAddress((void**)&bc,     g_bc);

    cudaFuncSetAttribute(gemm_fp8<0>, cudaFuncAttributeMaxDynamicSharedMemorySize, FP8_SMEM);
    cudaFuncSetAttribute(gemm_fp8<1>, cudaFuncAttributeMaxDynamicSharedMemorySize, FP8_SMEM);

    // 1) all prep + both LayerNorms, one grid
    prep_ln_kernel<<<7936, 256>>>(
        x, feat, qn_w, qn_b, fn_w, fn_b, Wv, Wout, Woff, boff, Waw, baw,
        qb8, fb8, wvt8, woutt8, wct8, bc);

    // 2) value GEMM + offaw GEMM fused (grid x: 6 value tiles + 1 offaw)
    gemm_fp8<0><<<dim3(7, BLn / 128), 256, FP8_SMEM>>>(
        fb8, wvt8, bv, val8, qb8, wct8, bc, oaw, nullptr, nullptr);

    // 3) softmax + bilinear sampling -> attn (e4m3)
    sample_kernel<<<(BLn * NHn) / 8, 256>>>(refp, oaw, val8, attn8);

    // 4) out = x + gamma * (attn @ Wout + bout)
    gemm_fp8<1><<<dim3(6, BLn / 128), 256, FP8_SMEM>>>(
        attn8, woutt8, bout, out, nullptr, nullptr, nullptr, nullptr, x, gamma);
}

// round 16
// speedup vs baseline: 1.0204x; 1.0204x over previous
#include <cuda_runtime.h>
#include <cuda_bf16.h>
#include <cuda_fp16.h>
#include <cuda_fp8.h>
#include <math.h>
#include <stdint.h>

// Problem constants
#define Bn   4
#define Ln   6400
#define Cn   768
#define NHn  6
#define NPn  4
#define DHn  128
#define HSn  80
#define WSn  80
#define BLn  (Bn * Ln)          // 25600 rows
#define OAW  72                 // 48 offset cols + 24 attn-weight cols

#define WSCALE     64.0f
#define INV_WSCALE (1.0f / 64.0f)

// ---------------------------------------------------------------------------
// Scratch (static device globals)
// ---------------------------------------------------------------------------
__device__ uint8_t g_qb8[BLn * Cn];     // layernorm(x), e4m3
__device__ uint8_t g_fb8[BLn * Cn];     // layernorm(feat), e4m3
__device__ uint8_t g_val8[BLn * Cn];    // value [B][NH][L][DH], e4m3
__device__ uint8_t g_attn8[BLn * Cn];   // sampled attn [B*L][C], e4m3
__device__ float   g_offaw[BLn * OAW];  // offsets+logits, fp32
__device__ uint8_t g_wvt8[Cn * Cn];     // (Wv*64)^T   [N][K] e4m3
__device__ uint8_t g_woutt8[Cn * Cn];   // (Wout*64)^T [N][K] e4m3
__device__ uint8_t g_wct8[128 * Cn];    // ([Woff|Waw|0]*64)^T [128][K] e4m3
__device__ float   g_bc[OAW];           // combined bias

// ---------------------------------------------------------------------------
// PTX helpers
// ---------------------------------------------------------------------------
__device__ __forceinline__ uint32_t s2u(const void* p) {
    uint32_t a;
    asm("{ .reg .u64 t; cvta.to.shared.u64 t, %1; cvt.u32.u64 %0, t; }"
        : "=r"(a) : "l"(p));
    return a;
}
__device__ __forceinline__ void ldsm_x4(uint32_t* r, uint32_t addr) {
    asm volatile("ldmatrix.sync.aligned.m8n8.x4.shared.b16 {%0,%1,%2,%3}, [%4];"
        : "=r"(r[0]), "=r"(r[1]), "=r"(r[2]), "=r"(r[3]) : "r"(addr));
}
__device__ __forceinline__ void mma_fp8(float* c, const uint32_t* a, const uint32_t* b) {
    asm volatile(
        "mma.sync.aligned.m16n8k32.row.col.f32.e4m3.e4m3.f32 "
        "{%0,%1,%2,%3}, {%4,%5,%6,%7}, {%8,%9}, {%0,%1,%2,%3};"
        : "+f"(c[0]), "+f"(c[1]), "+f"(c[2]), "+f"(c[3])
        : "r"(a[0]), "r"(a[1]), "r"(a[2]), "r"(a[3]), "r"(b[0]), "r"(b[1]));
}
__device__ __forceinline__ void cp16(uint32_t smem, const void* g) {
    asm volatile("cp.async.cg.shared.global [%0], [%1], 16;" :: "r"(smem), "l"(g));
}
#define CP_COMMIT()  asm volatile("cp.async.commit_group;" ::: "memory")
#define CP_WAIT1()   asm volatile("cp.async.wait_group 1;" ::: "memory")
#define CP_WAIT0()   asm volatile("cp.async.wait_group 0;" ::: "memory")

__device__ __forceinline__ uint32_t pack_fp8x4(float a, float b, float c, float d) {
    __nv_fp8x2_storage_t lo = __nv_cvt_float2_to_fp8x2(make_float2(a, b),
                                                       __NV_SATFINITE, __NV_E4M3);
    __nv_fp8x2_storage_t hi = __nv_cvt_float2_to_fp8x2(make_float2(c, d),
                                                       __NV_SATFINITE, __NV_E4M3);
    return (uint32_t)lo | ((uint32_t)hi << 16);
}
__device__ __forceinline__ float2 fp8x2_to_float2(uint16_t v) {
    __half2_raw h = __nv_cvt_fp8x2_to_halfraw2((__nv_fp8x2_storage_t)v, __NV_E4M3);
    return __half22float2(*reinterpret_cast<__half2*>(&h));
}

// 64B-pitch stage layout with XOR swizzle: chunk' = chunk ^ ((row>>1)&3).
// Conflict-free for ldmatrix reads and cp.async row writes.
__device__ __forceinline__ uint32_t swz64(int row, int chunk) {
    return (uint32_t)(row * 64 + ((chunk ^ ((row >> 1) & 3)) << 4));
}

// ---------------------------------------------------------------------------
// Fused prep + LayerNorm kernel. Flat blockIdx dispatch (see R10 notes).
// ---------------------------------------------------------------------------
__global__ void __launch_bounds__(256) prep_ln_kernel(
    const float* __restrict__ x,    const float* __restrict__ feat,
    const float* __restrict__ qn_w, const float* __restrict__ qn_b,
    const float* __restrict__ fn_w, const float* __restrict__ fn_b,
    const float* __restrict__ Wv,   const float* __restrict__ Wout,
    const float* __restrict__ Woff, const float* __restrict__ boff,
    const float* __restrict__ Waw,  const float* __restrict__ baw,
    uint8_t* __restrict__ qb8, uint8_t* __restrict__ fb8,
    uint8_t* __restrict__ wvt8, uint8_t* __restrict__ woutt8,
    uint8_t* __restrict__ wct8, float* __restrict__ bc)
{
    __shared__ float tsh[32 * 33];
    const int blk = blockIdx.x;
    const int tid = threadIdx.x;

    if (blk < 6400) {
        const float* in; const float* w; const float* b; uint8_t* out;
        int base;
        if (blk < 3200) { in = x;    w = qn_w; b = qn_b; out = qb8; base = blk; }
        else            { in = feat; w = fn_w; b = fn_b; out = fb8; base = blk - 3200; }
        const int wid = tid >> 5, lane = tid & 31;
        const int row = base * 8 + wid;
        const float4* p = (const float4*)(in + (size_t)row * Cn);

        float4 v[6];
        #pragma unroll
        for (int i = 0; i < 6; i++) v[i] = p[i * 32 + lane];
        float s1 = 0.f, s2 = 0.f;
        #pragma unroll
        for (int i = 0; i < 6; i++) {
            s1 += v[i].x + v[i].y + v[i].z + v[i].w;
            s2 += v[i].x * v[i].x + v[i].y * v[i].y
                + v[i].z * v[i].z + v[i].w * v[i].w;
        }
        #pragma unroll
        for (int o = 16; o > 0; o >>= 1) {
            s1 += __shfl_xor_sync(0xffffffffu, s1, o);
            s2 += __shfl_xor_sync(0xffffffffu, s2, o);
        }
        float mu = s1 * (1.0f / Cn);
        float rs = rsqrtf(s2 * (1.0f / Cn) - mu * mu + 1e-6f);

        const float4* wv = (const float4*)w;
        const float4* bv = (const float4*)b;
        uint32_t* o = (uint32_t*)(out + (size_t)row * Cn);
        #pragma unroll
        for (int i = 0; i < 6; i++) {
            float4 ww = wv[i * 32 + lane];
            float4 bb = bv[i * 32 + lane];
            o[i * 32 + lane] = pack_fp8x4(
                (v[i].x - mu) * rs * ww.x + bb.x,
                (v[i].y - mu) * rs * ww.y + bb.y,
                (v[i].z - mu) * rs * ww.z + bb.z,
                (v[i].w - mu) * rs * ww.w + bb.w);
        }
    } else if (blk < 7552) {
        const float* W;
        uint8_t* Wt;
        int t;
        if (blk < 6976) { W = Wv;   Wt = wvt8;   t = blk - 6400; }
        else            { W = Wout; Wt = woutt8; t = blk - 6976; }
        int bx = t % 24, by = t / 24;
        int tx = tid & 31, ty4 = tid >> 5;
        #pragma unroll
        for (int r = 0; r < 4; r++) {
            int ty = ty4 + r * 8;
            tsh[ty * 33 + tx] = W[(size_t)(by * 32 + ty) * Cn + bx * 32 + tx];
        }
        __syncthreads();
        #pragma unroll
        for (int r = 0; r < 4; r++) {
            int ty = ty4 + r * 8;
            Wt[(size_t)(bx * 32 + ty) * Cn + by * 32 + tx] =
                (uint8_t)__nv_cvt_float_to_fp8(tsh[tx * 33 + ty] * WSCALE,
                                               __NV_SATFINITE, __NV_E4M3);
        }
    } else {
        int idx = (blk - 7552) * 256 + tid;     // 0 .. 128*768-1
        int j = idx / Cn, k = idx % Cn;
        float v = 0.f;
        if (j < 48)       v = Woff[(size_t)k * 48 + j];
        else if (j < OAW) v = Waw[(size_t)k * 24 + (j - 48)];
        wct8[idx] = (uint8_t)__nv_cvt_float_to_fp8(v * WSCALE,
                                                   __NV_SATFINITE, __NV_E4M3);
        if (idx < OAW) bc[idx] = (idx < 48) ? boff[idx] : baw[idx - 48];
    }
}

// ---------------------------------------------------------------------------
// FP8 HMMA GEMM, CTA 128x128, BK=64/stage, 4-stage cp.async pipeline processed
// in PAIRS, 64B-pitch XOR-swizzled stages, hoisted ldmatrix offsets.
// __launch_bounds__(256,2): 2 CTAs/SM.
// STAGE 0 (grid 7 x 200): cCol 0..5 value GEMM, cCol 6 offaw GEMM. smem 64KB.
// STAGE 1 (grid 6 x 200): fused residual out GEMM; 88 of 128 x rows are
//   cp.async'd into SMEM during the mainloop -> epilogue mostly stores-only.
// ---------------------------------------------------------------------------
#define STG64  (128 * 64)            // 8192 B per matrix per stage
#define PAIRB  (2 * STG64)           // 16384 B per stage (A+B)
#define NIT    12
#define XROWS  88
#define XOFF   (4 * PAIRB)           // 65536: x region start
#define SMEM0  (4 * PAIRB)                    // 65536
#define SMEM1  (4 * PAIRB + XROWS * 512)      // 110592

template <int STAGE>
__global__ void __launch_bounds__(256, 2) gemm_fp8(
    const uint8_t* __restrict__ A0,   // stage0: fb8   | stage1: attn8
    const uint8_t* __restrict__ B0,   // stage0: wvt8  | stage1: woutt8
    const float* __restrict__ bias0,  // stage0: bv    | stage1: bout
    void* __restrict__ C0,            // stage0: val8  | stage1: out (fp32)
    const uint8_t* __restrict__ A1,   // stage0: qb8
    const uint8_t* __restrict__ B1,   // stage0: wct8
    const float* __restrict__ bias1,  // stage0: bc
    float* __restrict__ C1,           // stage0: oaw
    const float* __restrict__ xin,
    const float* __restrict__ gamma)
{
    extern __shared__ __align__(16) uint8_t dynsm[];

    const int tid  = threadIdx.x;
    const int wid  = tid >> 5, lane = tid & 31;
    const int wm   = wid & 3;
    const int wn   = wid >> 2;
    const int cCol = blockIdx.x, cRow = blockIdx.y;
    const bool off = (STAGE == 0) && (cCol == 6);

    const uint8_t* Ab = (off ? A1 : A0) + (size_t)cRow * 128 * Cn;
    const uint8_t* Bb = off ? B1 : (B0 + (size_t)cCol * 128 * Cn);
    const float* bias = off ? bias1 : bias0;
    const uint32_t smemBase = s2u(dynsm);

    const int row_c[2] = { tid >> 2, (tid + 256) >> 2 };
    const int q = tid & 3;
    const uint32_t sw0 = swz64(row_c[0], q);
    const uint32_t sw1 = swz64(row_c[1], q);

    auto issue = [&](int i) {
        uint32_t ab = smemBase + (uint32_t)(i & 3) * PAIRB;
        int k0 = i * 64;
        cp16(ab + sw0,         Ab + (size_t)row_c[0] * Cn + k0 + q * 16);
        cp16(ab + STG64 + sw0, Bb + (size_t)row_c[0] * Cn + k0 + q * 16);
        cp16(ab + sw1,         Ab + (size_t)row_c[1] * Cn + k0 + q * 16);
        cp16(ab + STG64 + sw1, Bb + (size_t)row_c[1] * Cn + k0 + q * 16);
    };

    float acc[2][8][4];
    #pragma unroll
    for (int mi = 0; mi < 2; mi++)
        #pragma unroll
        for (int n8 = 0; n8 < 8; n8++)
            #pragma unroll
            for (int j = 0; j < 4; j++) acc[mi][n8][j] = 0.f;

    // Hoisted per-lane ldmatrix offsets: logical chunk = base + 2*kidx
    const int lrow = lane & 7, grp = lane >> 3;
    const int rA = wm * 32 + (grp & 1) * 8 + lrow;
    const int cAc = grp >> 1;                 // A chunk base (0/1)
    const int rB = wn * 64 + ((lane >> 4) & 1) * 8 + lrow;
    const int cBc = grp & 1;                  // B chunk base (0/1)
    uint32_t oA[2][2], oB[4][2];
    #pragma unroll
    for (int mi = 0; mi < 2; mi++)
        #pragma unroll
        for (int kx = 0; kx < 2; kx++)
            oA[mi][kx] = swz64(rA + mi * 16, cAc + 2 * kx);
    #pragma unroll
    for (int nj = 0; nj < 4; nj++)
        #pragma unroll
        for (int kx = 0; kx < 2; kx++)
            oB[nj][kx] = STG64 + swz64(rB + nj * 16, cBc + 2 * kx);

    issue(0); CP_COMMIT();
    issue(1); CP_COMMIT();
    if (STAGE == 1) {
        // x prefetch: XROWS rows x 512B, one commit group (newest).
        const float* xb = xin + (size_t)(cRow * 128) * Cn + cCol * 128;
        uint32_t xs = smemBase + XOFF;
        #pragma unroll
        for (int j = 0; j < (XROWS * 32) / 256; j++) {   // 11 iters
            int idx = tid + j * 256;
            int row = idx >> 5, ch = idx & 31;
            cp16(xs + row * 512 + ch * 16, xb + (size_t)row * Cn + ch * 4);
        }
        CP_COMMIT();
    }

    for (int ip = 0; ip < NIT; ip += 2) {
        if (STAGE == 1 && ip == 0) { CP_WAIT1(); }  // allow x group to fly
        else                       { CP_WAIT0(); }
        __syncthreads();
        if (ip + 2 < NIT) {
            issue(ip + 2); CP_COMMIT();
            issue(ip + 3); CP_COMMIT();
        }
        #pragma unroll
        for (int d = 0; d < 2; d++) {
            uint32_t base = smemBase + (uint32_t)((ip + d) & 3) * PAIRB;
            #pragma unroll
            for (int kx = 0; kx < 2; kx++) {
                uint32_t afr[2][4], bfr[4][4];
                #pragma unroll
                for (int mi = 0; mi < 2; mi++)
                    ldsm_x4(afr[mi], base + oA[mi][kx]);
                #pragma unroll
                for (int nj = 0; nj < 4; nj++)
                    ldsm_x4(bfr[nj], base + oB[nj][kx]);
                #pragma unroll
                for (int mi = 0; mi < 2; mi++)
                    #pragma unroll
                    for (int n8 = 0; n8 < 8; n8++)
                        mma_fp8(acc[mi][n8], afr[mi], &bfr[n8 >> 1][(n8 & 1) * 2]);
            }
        }
    }

    // ---------------- epilogue ----------------
    const int quad = lane >> 2, tcol = (lane & 3) * 2;
    if (STAGE == 0 && off) {
        #pragma unroll
        for (int mi = 0; mi < 2; mi++) {
            #pragma unroll
            for (int n8 = 0; n8 < 8; n8++) {
                int colt = wn * 64 + n8 * 8 + tcol;
                if (colt >= OAW) continue;
                #pragma unroll
                for (int half = 0; half < 2; half++) {
                    int row = cRow * 128 + wm * 32 + mi * 16 + quad + half * 8;
                    float v0 = acc[mi][n8][half * 2 + 0] * INV_WSCALE;
                    float v1 = acc[mi][n8][half * 2 + 1] * INV_WSCALE;
                    float* dst = C1 + (size_t)row * OAW;
                    dst[colt] = v0 + bias[colt];
                    if (colt + 1 < OAW) dst[colt + 1] = v1 + bias[colt + 1];
                }
            }
        }
    } else if (STAGE == 0) {
        // value: stage fp8 tile in SMEM, then coalesced 16B row stores
        __syncthreads();
        uint8_t* st = dynsm;                 // [128][128] fp8
        #pragma unroll
        for (int mi = 0; mi < 2; mi++) {
            #pragma unroll
            for (int n8 = 0; n8 < 8; n8++) {
                int colt = wn * 64 + n8 * 8 + tcol;
                int col  = cCol * 128 + colt;
                #pragma unroll
                for (int half = 0; half < 2; half++) {
                    int rloc = wm * 32 + mi * 16 + quad + half * 8;
                    float f0 = acc[mi][n8][half * 2 + 0] * INV_WSCALE + bias[col];
                    float f1 = acc[mi][n8][half * 2 + 1] * INV_WSCALE + bias[col + 1];
                    __nv_fp8x2_storage_t p = __nv_cvt_float2_to_fp8x2(
                        make_float2(f0, f1), __NV_SATFINITE, __NV_E4M3);
                    *(uint16_t*)(st + rloc * 128 + colt) = (uint16_t)p;
                }
            }
        }
        __syncthreads();
        #pragma unroll
        for (int it = 0; it < 4; it++) {
            int idx  = tid + it * 256;       // 0..1023 (16B chunks)
            int rloc = idx >> 3, c16 = idx & 7;
            int m = cRow * 128 + rloc;
            int b = m / Ln, l = m % Ln;
            uint4 v = *(uint4*)(st + rloc * 128 + c16 * 16);
            *(uint4*)((uint8_t*)C0 +
                ((size_t)(b * NHn + cCol) * Ln + l) * DHn + c16 * 16) = v;
        }
    } else {
        // out = x + gamma * (acc/64 + bias); x rows < XROWS from SMEM
        #pragma unroll
        for (int mi = 0; mi < 2; mi++) {
            #pragma unroll
            for (int n8 = 0; n8 < 8; n8++) {
                int colt = wn * 64 + n8 * 8 + tcol;
                int col  = cCol * 128 + colt;
                #pragma unroll
                for (int half = 0; half < 2; half++) {
                    int rt  = wm * 32 + mi * 16 + quad + half * 8;  // tile row
                    int row = cRow * 128 + rt;
                    float v0 = acc[mi][n8][half * 2 + 0] * INV_WSCALE;
                    float v1 = acc[mi][n8][half * 2 + 1] * INV_WSCALE;
                    size_t idx = (size_t)row * Cn + col;
                    float2 xv;
                    if (rt < XROWS)
                        xv = *(const float2*)(dynsm + XOFF + rt * 512 + colt * 4);
                    else
                        xv = *(const float2*)(xin + idx);
                    float2 r;
                    r.x = xv.x + gamma[col]     * (v0 + bias[col]);
                    r.y = xv.y + gamma[col + 1] * (v1 + bias[col + 1]);
                    *(float2*)((float*)C0 + idx) = r;
                }
            }
        }
    }
}

// ---------------------------------------------------------------------------
// Bilinear sampling + softmax, branchless + batched gathers (MLP ~16).
// One warp per (b,l,h); lane owns 4 channels. value e4m3, attn e4m3.
// ---------------------------------------------------------------------------
__global__ void __launch_bounds__(256) sample_kernel(
    const float* __restrict__ refp, const float* __restrict__ offaw,
    const uint8_t* __restrict__ value, uint8_t* __restrict__ attn)
{
    int gw   = (blockIdx.x * 256 + threadIdx.x) >> 5;
    int lane = threadIdx.x & 31;
    if (gw >= BLn * NHn) return;
    int h  = gw % NHn;
    int bl = gw / NHn;
    int b  = bl / Ln;

    const float* oa = offaw + (size_t)bl * OAW;
    float lg0 = oa[48 + h * 4 + 0];
    float lg1 = oa[48 + h * 4 + 1];
    float lg2 = oa[48 + h * 4 + 2];
    float lg3 = oa[48 + h * 4 + 3];
    float mx = fmaxf(fmaxf(lg0, lg1), fmaxf(lg2, lg3));
    float e0 = expf(lg0 - mx), e1 = expf(lg1 - mx);
    float e2 = expf(lg2 - mx), e3 = expf(lg3 - mx);
    float inv = 1.0f / (e0 + e1 + e2 + e3);
    float aws[4] = {e0 * inv, e1 * inv, e2 * inv, e3 * inv};

    float rx = refp[bl * 2 + 0];
    float ry = refp[bl * 2 + 1];
    const uint8_t* vb = value + ((size_t)(b * NHn + h)) * Ln * DHn + lane * 4;

    const uint8_t* ptr[16];
    float wgt[16];
    #pragma unroll
    for (int p = 0; p < NPn; p++) {
        float ox = oa[h * 8 + p * 2 + 0];
        float oy = oa[h * 8 + p * 2 + 1];
        float lx = (rx + ox * (1.0f / WSn)) * (float)WSn - 0.5f;
        float ly = (ry + oy * (1.0f / HSn)) * (float)HSn - 0.5f;
        float x0f = floorf(lx), y0f = floorf(ly);
        float tx = lx - x0f, ty = ly - y0f;
        int x0 = (int)x0f, y0 = (int)y0f;
        float wp = aws[p];
        float cw[4] = {(1.f - tx) * (1.f - ty) * wp,
                       tx * (1.f - ty) * wp,
                       (1.f - tx) * ty * wp,
                       tx * ty * wp};
        #pragma unroll
        for (int c = 0; c < 4; c++) {
            int xi = x0 + (c & 1), yi = y0 + (c >> 1);
            bool valid = (xi >= 0) & (xi < WSn) & (yi >= 0) & (yi < HSn);
            int xc = min(max(xi, 0), WSn - 1);
            int yc = min(max(yi, 0), HSn - 1);
            ptr[p * 4 + c] = vb + (size_t)(yc * WSn + xc) * DHn;
            wgt[p * 4 + c] = valid ? cw[c] : 0.f;
        }
    }

    uint32_t pk[16];
    #pragma unroll
    for (int i = 0; i < 16; i++) pk[i] = *(const uint32_t*)ptr[i];

    float4 acc = make_float4(0.f, 0.f, 0.f, 0.f);
    #pragma unroll
    for (int i = 0; i < 16; i++) {
        float2 f01 = fp8x2_to_float2((uint16_t)(pk[i] & 0xffffu));
        float2 f23 = fp8x2_to_float2((uint16_t)(pk[i] >> 16));
        float w = wgt[i];
        acc.x += w * f01.x; acc.y += w * f01.y;
        acc.z += w * f23.x; acc.w += w * f23.y;
    }
    *(uint32_t*)(attn + (size_t)bl * Cn + h * DHn + lane * 4) =
        pack_fp8x4(acc.x, acc.y, acc.z, acc.w);
}

// ---------------------------------------------------------------------------
// Launch: 4 kernels total
// ---------------------------------------------------------------------------
extern "C" void kernel_launch(void* const* d_in, const int* in_sizes, int n_in,
                              void* d_out, int out_size)
{
    const float* x     = (const float*)d_in[0];
    const float* refp  = (const float*)d_in[1];
    const float* feat  = (const float*)d_in[2];
    const float* qn_w  = (const float*)d_in[5];
    const float* qn_b  = (const float*)d_in[6];
    const float* fn_w  = (const float*)d_in[7];
    const float* fn_b  = (const float*)d_in[8];
    const float* gamma = (const float*)d_in[9];
    const float* Wv    = (const float*)d_in[10];
    const float* bv    = (const float*)d_in[11];
    const float* Woff  = (const float*)d_in[12];
    const float* boff  = (const float*)d_in[13];
    const float* Waw   = (const float*)d_in[14];
    const float* baw   = (const float*)d_in[15];
    const float* Wout  = (const float*)d_in[16];
    const float* bout  = (const float*)d_in[17];
    float* out = (float*)d_out;

    uint8_t *qb8, *fb8, *val8, *attn8, *wvt8, *woutt8, *wct8;
    float *oaw, *bc;
    cudaGetSymbolAddress((void**)&qb8,    g_qb8);
    cudaGetSymbolAddress((void**)&fb8,    g_fb8);
    cudaGetSymbolAddress((void**)&val8,   g_val8);
    cudaGetSymbolAddress((void**)&attn8,  g_attn8);
    cudaGetSymbolAddress((void**)&oaw,    g_offaw);
    cudaGetSymbolAddress((void**)&wvt8,   g_wvt8);
    cudaGetSymbolAddress((void**)&woutt8, g_woutt8);
    cudaGetSymbolAddress((void**)&wct8,   g_wct8);
    cudaGetSymbolAddress((void**)&bc,     g_bc);

    cudaFuncSetAttribute(gemm_fp8<0>, cudaFuncAttributeMaxDynamicSharedMemorySize, SMEM0);
    cudaFuncSetAttribute(gemm_fp8<1>, cudaFuncAttributeMaxDynamicSharedMemorySize, SMEM1);

    // 1) all prep + both LayerNorms, one grid
    prep_ln_kernel<<<7936, 256>>>(
        x, feat, qn_w, qn_b, fn_w, fn_b, Wv, Wout, Woff, boff, Waw, baw,
        qb8, fb8, wvt8, woutt8, wct8, bc);

    // 2) value GEMM + offaw GEMM fused (grid x: 6 value tiles + 1 offaw)
    gemm_fp8<0><<<dim3(7, BLn / 128), 256, SMEM0>>>(
        fb8, wvt8, bv, val8, qb8, wct8, bc, oaw, nullptr, nullptr);

    // 3) softmax + bilinear sampling -> attn (e4m3)
    sample_kernel<<<(BLn * NHn) / 8, 256>>>(refp, oaw, val8, attn8);

    // 4) out = x + gamma * (attn @ Wout + bout), x prefetched to SMEM
    gemm_fp8<1><<<dim3(6, BLn / 128), 256, SMEM1>>>(
        attn8, woutt8, bout, out, nullptr, nullptr, nullptr, nullptr, x, gamma);
}